// round 14
// baseline (speedup 1.0000x reference)
#include <cuda_runtime.h>
#include <cstdint>

#define N_PTS   4096
#define DIM     128
#define TOPK    4

// ---------------- global scratch ----------------
__device__ float Z_buf[2 * N_PTS * DIM];                 // x @ W  (4 MB)
__device__ unsigned long long Top5x[2 * N_PTS * 16];     // per row: [half][8] exact sorted u64 keys (5 used)

#define BUBBLE5(k)                                            \
    { float _t, _k = (k);                                     \
      _t = fminf(s0, _k); _k = fmaxf(s0, _k); s0 = _t;        \
      _t = fminf(s1, _k); _k = fmaxf(s1, _k); s1 = _t;        \
      _t = fminf(s2, _k); _k = fmaxf(s2, _k); s2 = _t;        \
      _t = fminf(s3, _k); _k = fmaxf(s3, _k); s3 = _t;        \
      s4 = fminf(s4, _k); }

#define SWP(a,b) { unsigned long long _t; if (a > b) { _t = a; a = b; b = _t; } }

#define FMA_F32X2(acc, a, b) \
    asm("fma.rn.f32x2 %0, %1, %2, %3;" : "=l"(acc) : "l"(a), "l"(b), "l"(acc))

// ---------------- kernel 1: per-(32-row, 2048-cand-half) top-5 scan (R13, passed) ----------------
#define SB_THREADS 512
#define SB_WARPS   16
#define HALF_C     (N_PTS / 2)              // 2048
#define SB_SLICE   (HALF_C / SB_WARPS)      // 128
#define SB_L1      32

#define TREEMERGE()                                                        \
    _Pragma("unroll")                                                      \
    for (int step = 8; step >= 1; step >>= 1) {                            \
        if (warp >= step && warp < 2 * step) {                             \
            float* m = m_s + ((warp - step) * 32 + lane) * 5;              \
            m[0] = s0; m[1] = s1; m[2] = s2; m[3] = s3; m[4] = s4;         \
        }                                                                  \
        __syncthreads();                                                   \
        if (warp < step) {                                                 \
            const float* m = m_s + (warp * 32 + lane) * 5;                 \
            BUBBLE5(m[0]); BUBBLE5(m[1]); BUBBLE5(m[2]);                   \
            BUBBLE5(m[3]); BUBBLE5(m[4]);                                  \
        }                                                                  \
        __syncthreads();                                                   \
    }

__global__ void __launch_bounds__(SB_THREADS, 3)
scan_topk(const float* __restrict__ pos)
{
    extern __shared__ float smemB[];
    float4* pos_s  = (float4*)smemB;                   // [2048] (-2x,-2y,-2z,|q|^2)
    float*  m_s    = (float*)(pos_s + HALF_C);         // [8*32*5]
    float*  base_s = m_s + 8 * 32 * 5;                 // [32*5]
    float*  tau_s  = base_s + 32 * 5;                  // [32]

    const int tid  = threadIdx.x;
    const int warp = tid >> 5;
    const int lane = tid & 31;
    const int rg   = blockIdx.x >> 1;
    const int half = blockIdx.x & 1;
    const int r0   = rg * 32;
    const int b    = r0 >> 12;
    const int n0   = r0 & (N_PTS - 1);
    const int cb   = half * HALF_C;

    const float* pb = pos + ((size_t)b * N_PTS + cb) * 3;
    const float4* pb4 = (const float4*)pb;
    for (int g = tid; g < HALF_C / 4; g += SB_THREADS) {
        float4 a = pb4[3*g + 0];
        float4 c = pb4[3*g + 1];
        float4 d = pb4[3*g + 2];
        float px, py, pz; float4 q;
        px = a.x; py = a.y; pz = a.z;
        q.x = -2.f*px; q.y = -2.f*py; q.z = -2.f*pz;
        q.w = fmaf(pz, pz, fmaf(py, py, px * px));
        pos_s[4*g + 0] = q;
        px = a.w; py = c.x; pz = c.y;
        q.x = -2.f*px; q.y = -2.f*py; q.z = -2.f*pz;
        q.w = fmaf(pz, pz, fmaf(py, py, px * px));
        pos_s[4*g + 1] = q;
        px = c.z; py = c.w; pz = d.x;
        q.x = -2.f*px; q.y = -2.f*py; q.z = -2.f*pz;
        q.w = fmaf(pz, pz, fmaf(py, py, px * px));
        pos_s[4*g + 2] = q;
        px = d.y; py = d.z; pz = d.w;
        q.x = -2.f*px; q.y = -2.f*py; q.z = -2.f*pz;
        q.w = fmaf(pz, pz, fmaf(py, py, px * px));
        pos_s[4*g + 3] = q;
    }
    __syncthreads();

    const float* pr = pos + ((size_t)b * N_PTS + n0 + lane) * 3;
    float Px = __ldg(pr), Py = __ldg(pr + 1), Pz = __ldg(pr + 2);

    const float INF = __int_as_float(0x7f800000);
    float s0 = INF, s1 = INF, s2 = INF, s3 = INF, s4 = INF;

    const int base = warp * SB_SLICE;

    #pragma unroll 8
    for (int jj = 0; jj < SB_L1; jj++) {
        const int j = base + jj;
        float4 q = pos_s[j];
        float d2c = fmaf(Px, q.x, fmaf(Py, q.y, fmaf(Pz, q.z, q.w)));
        float k   = __int_as_float((__float_as_int(d2c) & 0xFFFFF000) | (cb + j));
        BUBBLE5(k);
    }

    TREEMERGE();

    if (warp == 0) {
        float* bs = base_s + lane * 5;
        bs[0] = s0; bs[1] = s1; bs[2] = s2; bs[3] = s3; bs[4] = s4;
        unsigned ub = __float_as_uint(s4);
        unsigned ut = ub & 0xFFFFF000u;
        ut = (ub & 0x80000000u) ? (ut - 0x1000u) : (ut + 0x1000u);
        tau_s[lane] = __uint_as_float(ut);
    }
    __syncthreads();

    const float tau = tau_s[lane];

    s0 = INF; s1 = INF; s2 = INF; s3 = INF; s4 = INF;
    #pragma unroll 8
    for (int jj = SB_L1; jj < SB_SLICE; jj++) {
        const int j = base + jj;
        float4 q = pos_s[j];
        float d2c = fmaf(Px, q.x, fmaf(Py, q.y, fmaf(Pz, q.z, q.w)));
        if (d2c < tau) {
            float k = __int_as_float((__float_as_int(d2c) & 0xFFFFF000) | (cb + j));
            BUBBLE5(k);
        }
    }

    TREEMERGE();

    if (warp == 0) {
        const float* bs = base_s + lane * 5;
        BUBBLE5(bs[0]); BUBBLE5(bs[1]); BUBBLE5(bs[2]);
        BUBBLE5(bs[3]); BUBBLE5(bs[4]);

        float cand[5] = { s0, s1, s2, s3, s4 };
        unsigned long long k[5];
        #pragma unroll
        for (int i = 0; i < 5; i++) {
            int jg = __float_as_int(cand[i]) & 0xFFF;
            float4 m = pos_s[jg - cb];
            float qx = -0.5f * m.x, qy = -0.5f * m.y, qz = -0.5f * m.z;
            float dx = Px - qx, dy = Py - qy, dz = Pz - qz;
            float d2 = fmaf(dz, dz, fmaf(dy, dy, dx * dx));
            k[i] = ((unsigned long long)__float_as_uint(d2) << 32) | (unsigned)jg;
        }
        SWP(k[0],k[1]) SWP(k[3],k[4]) SWP(k[2],k[4]) SWP(k[2],k[3]) SWP(k[0],k[3])
        SWP(k[0],k[2]) SWP(k[1],k[4]) SWP(k[1],k[3]) SWP(k[1],k[2])

        unsigned long long* dst = Top5x + ((size_t)(r0 + lane) * 2 + half) * 8;
        dst[0] = k[0]; dst[1] = k[1]; dst[2] = k[2];
        dst[3] = k[3]; dst[4] = k[4];
    }
}

// ---------------- kernel 2: Z = x @ W via f32x2, 32 rows x 64 cols / block ----------------
#define GA_THREADS 512

__global__ void __launch_bounds__(GA_THREADS, 3)
gemm_xw(const float* __restrict__ x, const float* __restrict__ W)
{
    extern __shared__ float smemA[];
    float2* w2_s = (float2*)smemA;                     // [64][64] float2 = 32 KB
    float*  x_s  = (float*)(w2_s + 64 * 64);           // [32][128] = 16 KB

    const int tid  = threadIdx.x;
    const int warp = tid >> 5;
    const int lane = tid & 31;
    const int gid  = blockIdx.x;                       // 0..511
    const int rg   = gid >> 1;
    const int colh = gid & 1;
    const int g0   = rg * 32;

    // W pairs: w2_s[t][cl] = (W[2t][c], W[2t+1][c]), c = colh*64+cl
    #pragma unroll
    for (int i = tid; i < 64 * 64; i += GA_THREADS) {
        int t = i >> 6, cl = i & 63;
        int c = colh * 64 + cl;
        float we = __ldg(&W[(2*t)     * DIM + c]);
        float wo = __ldg(&W[(2*t + 1) * DIM + c]);
        w2_s[t * 64 + cl] = make_float2(we, wo);
    }
    const float4* xg = (const float4*)x + (size_t)g0 * 32;
    float4* xs4 = (float4*)x_s;
    #pragma unroll
    for (int i = tid; i < 32 * 32; i += GA_THREADS) xs4[i] = xg[i];
    __syncthreads();

    const int r0l = warp * 2;                          // 2 rows per warp
    const unsigned long long* xr0 = (const unsigned long long*)(x_s + (r0l + 0) * DIM);
    const unsigned long long* xr1 = (const unsigned long long*)(x_s + (r0l + 1) * DIM);
    const ulonglong2* wv2 = (const ulonglong2*)w2_s;   // [64][32]

    unsigned long long a00 = 0, a01 = 0, a10 = 0, a11 = 0;

    #pragma unroll 16
    for (int t = 0; t < 64; t++) {
        ulonglong2 wp = wv2[t * 32 + lane];            // cols (2lane,2lane+1), LDS.128
        unsigned long long y0 = xr0[t];                // (x[r][2t], x[r][2t+1]), LDS.64
        unsigned long long y1 = xr1[t];
        FMA_F32X2(a00, y0, wp.x); FMA_F32X2(a01, y0, wp.y);
        FMA_F32X2(a10, y1, wp.x); FMA_F32X2(a11, y1, wp.y);
    }

    const int cg = colh * 64 + 2 * lane;
    float2* Z2 = (float2*)Z_buf;
    {
        float2 e, o, r;
        e = *(float2*)&a00; o = *(float2*)&a01;
        r.x = e.x + e.y; r.y = o.x + o.y;
        Z2[((size_t)(g0 + r0l + 0) * DIM + cg) >> 1] = r;
        e = *(float2*)&a10; o = *(float2*)&a11;
        r.x = e.x + e.y; r.y = o.x + o.y;
        Z2[((size_t)(g0 + r0l + 1) * DIM + cg) >> 1] = r;
    }
}

// ---------------- kernel 3: merge + weights + gather, 2 rows/warp ----------------
#define GC_THREADS 256
#define GC_WARPS   8           // 2 rows per warp -> 16 rows per block

__device__ __forceinline__ void merge_row(const unsigned long long* __restrict__ t,
                                          float& w0, float& w1, float& w2, float& w3,
                                          int& i0, int& i1, int& i2, int& i3)
{
    ulonglong2 a01 = __ldg((const ulonglong2*)(t + 0));
    ulonglong2 a23 = __ldg((const ulonglong2*)(t + 2));
    ulonglong2 b01 = __ldg((const ulonglong2*)(t + 8));
    ulonglong2 b23 = __ldg((const ulonglong2*)(t + 10));
    unsigned long long A0 = a01.x, A1 = a01.y, A2 = a23.x, A3 = a23.y;
    unsigned long long B0 = b01.x, B1 = b01.y, B2 = b23.x, B3 = b23.y;

    #pragma unroll
    for (int r = 0; r < TOPK; r++) {
        bool ta = A0 < B0;
        unsigned long long v = ta ? A0 : B0;
        if (ta) { A0 = A1; A1 = A2; A2 = A3; A3 = ~0ull; }
        else    { B0 = B1; B1 = B2; B2 = B3; B3 = ~0ull; }
        float d2 = __uint_as_float((unsigned)(v >> 32));
        float ww = expf(-0.5f * (d2 + 1e-8f));
        int   jj = (int)(v & 0xFFFFFFFFull);
        if      (r == 0) { w0 = ww; i0 = jj; }
        else if (r == 1) { w1 = ww; i1 = jj; }
        else if (r == 2) { w2 = ww; i2 = jj; }
        else             { w3 = ww; i3 = jj; }
    }
    float inv = 1.0f / (((w0 + w1) + w2) + w3 + 1e-8f);
    w0 *= inv; w1 *= inv; w2 *= inv; w3 *= inv;
}

__global__ void __launch_bounds__(GC_THREADS, 4)
finish_gather(const float* __restrict__ bias,
              float* __restrict__ out)
{
    const int tid  = threadIdx.x;
    const int warp = tid >> 5;
    const int lane = tid & 31;
    const int rowA = blockIdx.x * (GC_WARPS * 2) + warp * 2;
    const int rowB = rowA + 1;
    const int b    = rowA >> 12;    // rows in a block never straddle batches (16 | 4096)

    // two independent merge chains per warp (latency overlap)
    float wa0,wa1,wa2,wa3, wb0,wb1,wb2,wb3;
    int   ia0,ia1,ia2,ia3, ib0,ib1,ib2,ib3;
    merge_row(Top5x + (size_t)rowA * 16, wa0,wa1,wa2,wa3, ia0,ia1,ia2,ia3);
    merge_row(Top5x + (size_t)rowB * 16, wb0,wb1,wb2,wb3, ib0,ib1,ib2,ib3);

    const float4* Z4 = (const float4*)Z_buf + (size_t)b * N_PTS * 32;
    const float4  bv = __ldg(&((const float4*)bias)[lane]);

    // issue all 8 Z-row loads, then FMA
    float4 za0 = Z4[(size_t)ia0 * 32 + lane];
    float4 za1 = Z4[(size_t)ia1 * 32 + lane];
    float4 za2 = Z4[(size_t)ia2 * 32 + lane];
    float4 za3 = Z4[(size_t)ia3 * 32 + lane];
    float4 zb0 = Z4[(size_t)ib0 * 32 + lane];
    float4 zb1 = Z4[(size_t)ib1 * 32 + lane];
    float4 zb2 = Z4[(size_t)ib2 * 32 + lane];
    float4 zb3 = Z4[(size_t)ib3 * 32 + lane];

    float4 accA = bv, accB = bv;
    accA.x = fmaf(wa0,za0.x, fmaf(wa1,za1.x, fmaf(wa2,za2.x, fmaf(wa3,za3.x, accA.x))));
    accA.y = fmaf(wa0,za0.y, fmaf(wa1,za1.y, fmaf(wa2,za2.y, fmaf(wa3,za3.y, accA.y))));
    accA.z = fmaf(wa0,za0.z, fmaf(wa1,za1.z, fmaf(wa2,za2.z, fmaf(wa3,za3.z, accA.z))));
    accA.w = fmaf(wa0,za0.w, fmaf(wa1,za1.w, fmaf(wa2,za2.w, fmaf(wa3,za3.w, accA.w))));
    accB.x = fmaf(wb0,zb0.x, fmaf(wb1,zb1.x, fmaf(wb2,zb2.x, fmaf(wb3,zb3.x, accB.x))));
    accB.y = fmaf(wb0,zb0.y, fmaf(wb1,zb1.y, fmaf(wb2,zb2.y, fmaf(wb3,zb3.y, accB.y))));
    accB.z = fmaf(wb0,zb0.z, fmaf(wb1,zb1.z, fmaf(wb2,zb2.z, fmaf(wb3,zb3.z, accB.z))));
    accB.w = fmaf(wb0,zb0.w, fmaf(wb1,zb1.w, fmaf(wb2,zb2.w, fmaf(wb3,zb3.w, accB.w))));

    ((float4*)out)[(size_t)rowA * 32 + lane] = accA;
    ((float4*)out)[(size_t)rowB * 32 + lane] = accB;
}

extern "C" void kernel_launch(void* const* d_in, const int* in_sizes, int n_in,
                              void* d_out, int out_size)
{
    const float* x    = (const float*)d_in[0];
    const float* pos  = (const float*)d_in[1];
    const float* W    = (const float*)d_in[2];
    const float* bias = (const float*)d_in[3];
    float* out        = (float*)d_out;

    const int rows = in_sizes[1] / 3;                  // B * N = 8192

    // K1: top-5 scan (512 blocks)
    const size_t smemB = (size_t)HALF_C * 16 + 8*32*5*4 + 32*5*4 + 32*4;   // 38656
    cudaFuncSetAttribute(scan_topk, cudaFuncAttributeMaxDynamicSharedMemorySize, (int)smemB);
    scan_topk<<<(rows / 32) * 2, SB_THREADS, smemB>>>(pos);

    // K2: Z = x @ W (512 blocks, f32x2, 32 rows x 64 cols)
    const size_t smemA = (size_t)64 * 64 * 8 + (size_t)32 * DIM * 4;       // 49152
    cudaFuncSetAttribute(gemm_xw, cudaFuncAttributeMaxDynamicSharedMemorySize, (int)smemA);
    gemm_xw<<<(rows / 32) * 2, GA_THREADS, smemA>>>(x, W);

    // K3: merge + weights + gather (2 rows per warp)
    finish_gather<<<rows / (GC_WARPS * 2), GC_THREADS>>>(bias, out);
}

// round 15
// speedup vs baseline: 1.1438x; 1.1438x over previous
#include <cuda_runtime.h>
#include <cstdint>

#define N_PTS   4096
#define DIM     128
#define TOPK    4

// ---------------- global scratch ----------------
__device__ float Z_buf[2 * N_PTS * DIM];   // x @ W  (4 MB), row-major [8192][128]

#define FMA_F32X2(acc, a, b) \
    asm("fma.rn.f32x2 %0, %1, %2, %3;" : "=l"(acc) : "l"(a), "l"(b), "l"(acc))

// ---------------- kernel 1: Z = x @ W via packed f32x2 (R13, measured ~8.5us) ----------------
// Block: 64 rows x 64 cols (colh). Accum halves = even-d / odd-d sums.

#define GA_THREADS 512

__global__ void __launch_bounds__(GA_THREADS, 2)
gemm_xw(const float* __restrict__ x, const float* __restrict__ W)
{
    extern __shared__ float smemA[];
    float2* w2_s = (float2*)smemA;                     // [64][64] float2 = 32 KB
    float*  x_s  = (float*)(w2_s + 64 * 64);           // [64][128] = 32 KB

    const int tid  = threadIdx.x;
    const int warp = tid >> 5;
    const int lane = tid & 31;
    const int gid  = blockIdx.x;                       // 0..255
    const int rg   = gid >> 1;
    const int colh = gid & 1;
    const int g0   = rg * 64;

    // W pairs: w2_s[t][cl] = (W[2t][c], W[2t+1][c]), c = colh*64+cl
    #pragma unroll
    for (int i = tid; i < 64 * 64; i += GA_THREADS) {
        int t = i >> 6, cl = i & 63;
        int c = colh * 64 + cl;
        float we = __ldg(&W[(2*t)     * DIM + c]);
        float wo = __ldg(&W[(2*t + 1) * DIM + c]);
        w2_s[t * 64 + cl] = make_float2(we, wo);
    }
    const float4* xg = (const float4*)x + (size_t)g0 * 32;
    float4* xs4 = (float4*)x_s;
    #pragma unroll
    for (int i = tid; i < 64 * 32; i += GA_THREADS) xs4[i] = xg[i];
    __syncthreads();

    const int r0l = warp * 4;                          // 4 rows per warp
    const unsigned long long* xr0 = (const unsigned long long*)(x_s + (r0l + 0) * DIM);
    const unsigned long long* xr1 = (const unsigned long long*)(x_s + (r0l + 1) * DIM);
    const unsigned long long* xr2 = (const unsigned long long*)(x_s + (r0l + 2) * DIM);
    const unsigned long long* xr3 = (const unsigned long long*)(x_s + (r0l + 3) * DIM);
    const ulonglong2* wv2 = (const ulonglong2*)w2_s;   // [64][32]

    unsigned long long a00 = 0, a01 = 0, a10 = 0, a11 = 0;
    unsigned long long a20 = 0, a21 = 0, a30 = 0, a31 = 0;

    #pragma unroll 8
    for (int t = 0; t < 64; t++) {
        ulonglong2 wp = wv2[t * 32 + lane];            // cols (2lane,2lane+1), LDS.128
        unsigned long long y0 = xr0[t];                // (x[r][2t], x[r][2t+1]), LDS.64
        unsigned long long y1 = xr1[t];
        unsigned long long y2 = xr2[t];
        unsigned long long y3 = xr3[t];
        FMA_F32X2(a00, y0, wp.x); FMA_F32X2(a01, y0, wp.y);
        FMA_F32X2(a10, y1, wp.x); FMA_F32X2(a11, y1, wp.y);
        FMA_F32X2(a20, y2, wp.x); FMA_F32X2(a21, y2, wp.y);
        FMA_F32X2(a30, y3, wp.x); FMA_F32X2(a31, y3, wp.y);
    }

    const int cg = colh * 64 + 2 * lane;
    float2* Z2 = (float2*)Z_buf;
    {
        float2 e, o, r;
        #define STORE_ROW(ar0, ar1, rr)                                        \
        {                                                                      \
            e = *(float2*)&ar0; o = *(float2*)&ar1;                            \
            r.x = e.x + e.y;                                                   \
            r.y = o.x + o.y;                                                   \
            Z2[((size_t)(g0 + r0l + rr) * DIM + cg) >> 1] = r;                 \
        }
        STORE_ROW(a00, a01, 0)
        STORE_ROW(a10, a11, 1)
        STORE_ROW(a20, a21, 2)
        STORE_ROW(a30, a31, 3)
        #undef STORE_ROW
    }
}

// ---------------- kernel 2: fused top-4 scan + merge + rerank + gather (R6, 28.7us) ----------------
#define GB_THREADS 512
#define GB_WARPS   16
#define SLICE      (N_PTS / GB_WARPS)      // 256
#define L1SCAN     64                      // phase-1 candidates per warp
#define GB_ROWS    32

#define BUBBLE5(k)                                            \
    { float _t, _k = (k);                                     \
      _t = fminf(s0, _k); _k = fmaxf(s0, _k); s0 = _t;        \
      _t = fminf(s1, _k); _k = fmaxf(s1, _k); s1 = _t;        \
      _t = fminf(s2, _k); _k = fmaxf(s2, _k); s2 = _t;        \
      _t = fminf(s3, _k); _k = fmaxf(s3, _k); s3 = _t;        \
      s4 = fminf(s4, _k); }

#define TREEMERGE()                                                        \
    _Pragma("unroll")                                                      \
    for (int step = 8; step >= 1; step >>= 1) {                            \
        if (warp >= step && warp < 2 * step) {                             \
            float* m = m_s + ((warp - step) * 32 + lane) * 5;              \
            m[0] = s0; m[1] = s1; m[2] = s2; m[3] = s3; m[4] = s4;         \
        }                                                                  \
        __syncthreads();                                                   \
        if (warp < step) {                                                 \
            const float* m = m_s + (warp * 32 + lane) * 5;                 \
            BUBBLE5(m[0]); BUBBLE5(m[1]); BUBBLE5(m[2]);                   \
            BUBBLE5(m[3]); BUBBLE5(m[4]);                                  \
        }                                                                  \
        __syncthreads();                                                   \
    }

#define SWP(a,b) { unsigned long long _t; if (a > b) { _t = a; a = b; b = _t; } }

__global__ void __launch_bounds__(GB_THREADS, 3)
topk_gather(const float* __restrict__ pos,
            const float* __restrict__ bias,
            float* __restrict__ out)
{
    extern __shared__ float smemB[];
    float4* pos_s  = (float4*)smemB;                   // [4096] .w = -0.5*|p|^2
    float*  m_s    = (float*)(pos_s + N_PTS);          // [8*32*5] tree-merge staging
    float*  base_s = m_s + 8 * 32 * 5;                 // [32*5] phase-1 block top-5
    float*  tau_s  = base_s + 32 * 5;                  // [32] thresholds
    float*  w_s    = tau_s + 32;                       // [32*4] weights
    int*    idx_s  = (int*)(w_s + 32 * 4);             // [32*4] indices

    const int tid  = threadIdx.x;
    const int warp = tid >> 5;
    const int lane = tid & 31;
    const int r0   = blockIdx.x * GB_ROWS;
    const int b    = r0 >> 12;
    const int n0   = r0 & (N_PTS - 1);

    // ---- load pos for this batch ----
    const float4* pb4 = (const float4*)(pos + (size_t)b * N_PTS * 3);
    for (int g = tid; g < N_PTS / 4; g += GB_THREADS) {
        float4 a = pb4[3*g + 0];
        float4 c = pb4[3*g + 1];
        float4 d = pb4[3*g + 2];
        float4 q;
        q.x = a.x; q.y = a.y; q.z = a.z;
        q.w = -0.5f * fmaf(q.z, q.z, fmaf(q.y, q.y, q.x * q.x));
        pos_s[4*g + 0] = q;
        q.x = a.w; q.y = c.x; q.z = c.y;
        q.w = -0.5f * fmaf(q.z, q.z, fmaf(q.y, q.y, q.x * q.x));
        pos_s[4*g + 1] = q;
        q.x = c.z; q.y = c.w; q.z = d.x;
        q.w = -0.5f * fmaf(q.z, q.z, fmaf(q.y, q.y, q.x * q.x));
        pos_s[4*g + 2] = q;
        q.x = d.y; q.y = d.z; q.z = d.w;
        q.w = -0.5f * fmaf(q.z, q.z, fmaf(q.y, q.y, q.x * q.x));
        pos_s[4*g + 3] = q;
    }
    __syncthreads();

    const float4 P   = pos_s[n0 + lane];
    const float  Pw2 = -2.0f * P.w;                    // |pi|^2

    const float INF = __int_as_float(0x7f800000);
    float s0 = INF, s1 = INF, s2 = INF, s3 = INF, s4 = INF;

    const int base = warp * SLICE;

    // ---- phase 1: unconditional bubble over first L1SCAN of the slice ----
    #pragma unroll 8
    for (int jj = 0; jj < L1SCAN; jj++) {
        const int j = base + jj;
        float4 q = pos_s[j];
        float t   = fmaf(P.x, q.x, fmaf(P.y, q.y, fmaf(P.z, q.z, q.w)));
        float d2c = fmaf(-2.0f, t, Pw2);
        float k   = __int_as_float((__float_as_int(d2c) & 0xFFFFF000) | j);
        BUBBLE5(k);
    }

    // ---- merge phase-1 results -> block top-5 of 1024 samples (in warp 0) ----
    TREEMERGE();

    if (warp == 0) {
        float* bs = base_s + lane * 5;
        bs[0] = s0; bs[1] = s1; bs[2] = s2; bs[3] = s3; bs[4] = s4;
        tau_s[lane] = __int_as_float((__float_as_int(s4) & 0xFFFFF000) + 0x1000);
    }
    __syncthreads();

    const float tau = tau_s[lane];

    // ---- phase 2: filtered scan of the rest of the slice ----
    s0 = INF; s1 = INF; s2 = INF; s3 = INF; s4 = INF;
    #pragma unroll 8
    for (int jj = L1SCAN; jj < SLICE; jj++) {
        const int j = base + jj;
        float4 q = pos_s[j];
        float t   = fmaf(P.x, q.x, fmaf(P.y, q.y, fmaf(P.z, q.z, q.w)));
        float d2c = fmaf(-2.0f, t, Pw2);
        if (d2c < tau) {                               // ~0.5% per lane
            float k = __int_as_float((__float_as_int(d2c) & 0xFFFFF000) | j);
            BUBBLE5(k);
        }
    }

    // ---- merge phase-2 survivors, fold in base-5, rerank exactly ----
    TREEMERGE();

    if (warp == 0) {
        const float* bs = base_s + lane * 5;
        BUBBLE5(bs[0]); BUBBLE5(bs[1]); BUBBLE5(bs[2]);
        BUBBLE5(bs[3]); BUBBLE5(bs[4]);

        float cand[5] = { s0, s1, s2, s3, s4 };
        unsigned long long k[5];
        #pragma unroll
        for (int i = 0; i < 5; i++) {
            int j = __float_as_int(cand[i]) & 0xFFF;
            float4 q = pos_s[j];
            float dx = P.x - q.x, dy = P.y - q.y, dz = P.z - q.z;
            float d2 = fmaf(dz, dz, fmaf(dy, dy, dx * dx));
            k[i] = ((unsigned long long)__float_as_uint(d2) << 32) | (unsigned)j;
        }
        SWP(k[0],k[1]) SWP(k[3],k[4]) SWP(k[2],k[4]) SWP(k[2],k[3]) SWP(k[0],k[3])
        SWP(k[0],k[2]) SWP(k[1],k[4]) SWP(k[1],k[3]) SWP(k[1],k[2])

        float wgt[TOPK];
        #pragma unroll
        for (int r = 0; r < TOPK; r++) {
            float d2 = __uint_as_float((unsigned)(k[r] >> 32));
            wgt[r]   = expf(-0.5f * (d2 + 1e-8f));
            idx_s[lane * TOPK + r] = (int)(k[r] & 0xFFFFFFFFull);
        }
        float inv = 1.0f / (((wgt[0] + wgt[1]) + wgt[2]) + wgt[3] + 1e-8f);
        #pragma unroll
        for (int r = 0; r < TOPK; r++) w_s[lane * TOPK + r] = wgt[r] * inv;
    }
    __syncthreads();

    // ---- gather: 16 warps x 2 rows; 32 lanes cover the 128 outputs ----
    const float4* Z4 = (const float4*)Z_buf + (size_t)b * N_PTS * 32;
    const float4  bv = ((const float4*)bias)[lane];
    float4* out4 = (float4*)out;

    #pragma unroll
    for (int rr = warp; rr < GB_ROWS; rr += GB_WARPS) {
        float w0 = w_s[rr*4+0], w1 = w_s[rr*4+1], w2 = w_s[rr*4+2], w3 = w_s[rr*4+3];
        int   i0 = idx_s[rr*4+0], i1 = idx_s[rr*4+1], i2 = idx_s[rr*4+2], i3 = idx_s[rr*4+3];
        float4 z0 = Z4[(size_t)i0 * 32 + lane];
        float4 z1 = Z4[(size_t)i1 * 32 + lane];
        float4 z2 = Z4[(size_t)i2 * 32 + lane];
        float4 z3 = Z4[(size_t)i3 * 32 + lane];
        float4 acc = bv;
        acc.x = fmaf(w0,z0.x, fmaf(w1,z1.x, fmaf(w2,z2.x, fmaf(w3,z3.x, acc.x))));
        acc.y = fmaf(w0,z0.y, fmaf(w1,z1.y, fmaf(w2,z2.y, fmaf(w3,z3.y, acc.y))));
        acc.z = fmaf(w0,z0.z, fmaf(w1,z1.z, fmaf(w2,z2.z, fmaf(w3,z3.z, acc.z))));
        acc.w = fmaf(w0,z0.w, fmaf(w1,z1.w, fmaf(w2,z2.w, fmaf(w3,z3.w, acc.w))));
        out4[(size_t)(r0 + rr) * 32 + lane] = acc;
    }
}

extern "C" void kernel_launch(void* const* d_in, const int* in_sizes, int n_in,
                              void* d_out, int out_size)
{
    const float* x    = (const float*)d_in[0];
    const float* pos  = (const float*)d_in[1];
    const float* W    = (const float*)d_in[2];
    const float* bias = (const float*)d_in[3];
    float* out        = (float*)d_out;

    const int rows = in_sizes[1] / 3;                  // B * N = 8192

    // K1: Z = x @ W (f32x2, 64x64 tiles, 256 blocks)
    const size_t smemA = (size_t)64 * 64 * 8 + (size_t)64 * DIM * 4;       // 65536
    cudaFuncSetAttribute(gemm_xw, cudaFuncAttributeMaxDynamicSharedMemorySize, (int)smemA);
    gemm_xw<<<(rows / 64) * 2, GA_THREADS, smemA>>>(x, W);

    // K2: fused top-4 + gather (R6)
    const size_t smemB = (size_t)N_PTS * 16            // pos_s        65536
                       + 8 * 32 * 5 * 4                // m_s           5120
                       + 32 * 5 * 4                    // base_s         640
                       + 32 * 4                        // tau_s          128
                       + 32 * 4 * 4                    // w_s            512
                       + 32 * 4 * 4;                   // idx_s          512
    cudaFuncSetAttribute(topk_gather, cudaFuncAttributeMaxDynamicSharedMemorySize, (int)smemB);
    topk_gather<<<rows / GB_ROWS, GB_THREADS, smemB>>>(pos, bias, out);
}